// round 10
// baseline (speedup 1.0000x reference)
#include <cuda_runtime.h>
#include <cstdint>

#define NSEQ 128
#define TB   4096
#define FIN  208
#define HGRU 131
#define HP   132      // activation pitch (g_x)
#define HPW  136      // W_hh row / h pitch: 68 pairs = 4 x 17
#define G3   393      // 3*H
#define G3P  416      // padded 3*H
#define DMLP 255
#define DOUT 17

#define GBLK 544      // GRU: 136 units x 4 K-quarters (17 warps)

typedef unsigned long long ull;

// ---- scratch (__device__ globals; zero-initialized; pads never written) ----
__device__ float g_wpad[G3 * HPW];       // W_hh padded [393][136]
__device__ float g_gi[NSEQ * G3];
__device__ float g_x[NSEQ * HP];         // GRU outputs, pitch 132
__device__ float g_wiht[FIN * G3P];      // W_ih^T [208][416]
__device__ float g_bihp[G3P];
__device__ float g_wmt[5][256 * 256];    // W1..W5 transposed [k][c]
__device__ float g_bmp[5][256];
__device__ float g_w6t[256 * 32];        // W6^T [k][c]
__device__ float g_b6p[32];

// ---- prep: coalesced reads, scattered writes ----
__global__ void prep_kernel(const float* __restrict__ Whh,
                            const float* __restrict__ Wih,
                            const float* __restrict__ bih,
                            const float* __restrict__ W1, const float* __restrict__ b1,
                            const float* __restrict__ W2, const float* __restrict__ b2,
                            const float* __restrict__ W3, const float* __restrict__ b3,
                            const float* __restrict__ W4, const float* __restrict__ b4,
                            const float* __restrict__ W5, const float* __restrict__ b5,
                            const float* __restrict__ W6, const float* __restrict__ b6)
{
    int idx = blockIdx.x * blockDim.x + threadIdx.x;

    if (idx < G3 * HGRU) {
        int j = idx / HGRU, k = idx - j * HGRU;
        g_wpad[j * HPW + k] = Whh[idx];
        return;
    }
    idx -= G3 * HGRU;
    if (idx < G3 * FIN) {
        int j = idx / FIN, k = idx - j * FIN;
        g_wiht[k * G3P + j] = Wih[idx];
        return;
    }
    idx -= G3 * FIN;
    if (idx < G3) { g_bihp[idx] = bih[idx]; return; }
    idx -= G3;
    if (idx < DMLP * HGRU) {
        int c = idx / HGRU, k = idx - c * HGRU;
        g_wmt[0][k * 256 + c] = W1[idx];
        return;
    }
    idx -= DMLP * HGRU;
    if (idx < 4 * DMLP * DMLP) {
        int l = idx / (DMLP * DMLP);
        int r = idx - l * (DMLP * DMLP);
        int c = r / DMLP, k = r - c * DMLP;
        const float* W = (l == 0) ? W2 : (l == 1) ? W3 : (l == 2) ? W4 : W5;
        g_wmt[l + 1][k * 256 + c] = W[r];
        return;
    }
    idx -= 4 * DMLP * DMLP;
    if (idx < 5 * DMLP) {
        int l = idx / DMLP, c = idx - l * DMLP;
        const float* B = (l == 0) ? b1 : (l == 1) ? b2 : (l == 2) ? b3
                        : (l == 3) ? b4 : b5;
        g_bmp[l][c] = B[c];
        return;
    }
    idx -= 5 * DMLP;
    if (idx < DOUT * DMLP) {
        int c = idx / DMLP, k = idx - c * DMLP;
        g_w6t[k * 32 + c] = W6[idx];
        return;
    }
    idx -= DOUT * DMLP;
    if (idx < DOUT) g_b6p[idx] = b6[idx];
}

// ---- gi projection ----
__global__ __launch_bounds__(G3P) void gi_kernel(const float* __restrict__ hist)
{
    __shared__ float2 xs[FIN];
    const int j = threadIdx.x;
    const int r0 = blockIdx.x * 2;

    const float* h0 = hist + ((size_t)r0 * TB + (TB - 1)) * FIN;
    const float* h1 = hist + ((size_t)(r0 + 1) * TB + (TB - 1)) * FIN;
    for (int k = j; k < FIN; k += G3P) xs[k] = make_float2(h0[k], h1[k]);
    __syncthreads();

    float bv = g_bihp[j];
    float a0 = bv, a1 = bv;
#pragma unroll 16
    for (int k = 0; k < FIN; k++) {
        float w = g_wiht[k * G3P + j];
        float2 x = xs[k];
        a0 = fmaf(x.x, w, a0);
        a1 = fmaf(x.y, w, a1);
    }
    if (j < G3) {
        g_gi[r0 * G3 + j]       = a0;
        g_gi[(r0 + 1) * G3 + j] = a1;
    }
}

// ---- fused 6-layer MLP (unchanged from R9): 512 thr, staged 8-load batches --
__global__ __launch_bounds__(512) void mlp_kernel(float* __restrict__ out)
{
    __shared__ float2 xbuf[256];
    __shared__ float4 red[8][64][2];
    const int tid = threadIdx.x;
    const int cg = tid & 63;
    const int ks = tid >> 6;
    const int r0 = blockIdx.x * 2;
    const int kbase = ks * 32;

    if (tid < 256) {
        float2 v = make_float2(0.f, 0.f);
        if (tid < HGRU)
            v = make_float2(g_x[r0 * HP + tid], g_x[(r0 + 1) * HP + tid]);
        xbuf[tid] = v;
    }
    __syncthreads();

#pragma unroll
    for (int l = 0; l < 5; l++) {
        const float4* wt4 = reinterpret_cast<const float4*>(g_wmt[l]);
        float4 a0 = make_float4(0.f, 0.f, 0.f, 0.f);
        float4 a1 = a0;
#pragma unroll
        for (int g = 0; g < 4; g++) {
            float4 wb[8];
            float2 xb[8];
#pragma unroll
            for (int u = 0; u < 8; u++) {
                int k = kbase + g * 8 + u;
                wb[u] = wt4[k * 64 + cg];
                xb[u] = xbuf[k];
            }
#pragma unroll
            for (int u = 0; u < 8; u++) {
                a0.x = fmaf(xb[u].x, wb[u].x, a0.x);
                a0.y = fmaf(xb[u].x, wb[u].y, a0.y);
                a0.z = fmaf(xb[u].x, wb[u].z, a0.z);
                a0.w = fmaf(xb[u].x, wb[u].w, a0.w);
                a1.x = fmaf(xb[u].y, wb[u].x, a1.x);
                a1.y = fmaf(xb[u].y, wb[u].y, a1.y);
                a1.z = fmaf(xb[u].y, wb[u].z, a1.z);
                a1.w = fmaf(xb[u].y, wb[u].w, a1.w);
            }
        }
        red[ks][cg][0] = a0;
        red[ks][cg][1] = a1;
        __syncthreads();
        if (ks == 0) {
            float4 s0 = red[0][cg][0], s1 = red[0][cg][1];
#pragma unroll
            for (int q = 1; q < 8; q++) {
                float4 t0 = red[q][cg][0], t1 = red[q][cg][1];
                s0.x += t0.x; s0.y += t0.y; s0.z += t0.z; s0.w += t0.w;
                s1.x += t1.x; s1.y += t1.y; s1.z += t1.z; s1.w += t1.w;
            }
            float4 b = reinterpret_cast<const float4*>(g_bmp[l])[cg];
            xbuf[4 * cg + 0] = make_float2(fmaxf(s0.x + b.x, 0.f), fmaxf(s1.x + b.x, 0.f));
            xbuf[4 * cg + 1] = make_float2(fmaxf(s0.y + b.y, 0.f), fmaxf(s1.y + b.y, 0.f));
            xbuf[4 * cg + 2] = make_float2(fmaxf(s0.z + b.z, 0.f), fmaxf(s1.z + b.z, 0.f));
            xbuf[4 * cg + 3] = make_float2(fmaxf(s0.w + b.w, 0.f), fmaxf(s1.w + b.w, 0.f));
        }
        __syncthreads();
    }

    {
        const float4* w6 = reinterpret_cast<const float4*>(g_w6t);
        float4 a0 = make_float4(0.f, 0.f, 0.f, 0.f);
        float4 a1 = a0;
        if (cg < 8) {
#pragma unroll
            for (int g = 0; g < 4; g++) {
                float4 wb[8];
                float2 xb[8];
#pragma unroll
                for (int u = 0; u < 8; u++) {
                    int k = kbase + g * 8 + u;
                    wb[u] = w6[k * 8 + cg];
                    xb[u] = xbuf[k];
                }
#pragma unroll
                for (int u = 0; u < 8; u++) {
                    a0.x = fmaf(xb[u].x, wb[u].x, a0.x);
                    a0.y = fmaf(xb[u].x, wb[u].y, a0.y);
                    a0.z = fmaf(xb[u].x, wb[u].z, a0.z);
                    a0.w = fmaf(xb[u].x, wb[u].w, a0.w);
                    a1.x = fmaf(xb[u].y, wb[u].x, a1.x);
                    a1.y = fmaf(xb[u].y, wb[u].y, a1.y);
                    a1.z = fmaf(xb[u].y, wb[u].z, a1.z);
                    a1.w = fmaf(xb[u].y, wb[u].w, a1.w);
                }
            }
        }
        red[ks][cg][0] = a0;
        red[ks][cg][1] = a1;
        __syncthreads();
        if (ks == 0 && cg < 5) {
            float4 s0 = red[0][cg][0], s1 = red[0][cg][1];
#pragma unroll
            for (int q = 1; q < 8; q++) {
                float4 t0 = red[q][cg][0], t1 = red[q][cg][1];
                s0.x += t0.x; s0.y += t0.y; s0.z += t0.z; s0.w += t0.w;
                s1.x += t1.x; s1.y += t1.y; s1.z += t1.z; s1.w += t1.w;
            }
            float4 b = reinterpret_cast<const float4*>(g_b6p)[cg];
            float o0[4] = {s0.x + b.x, s0.y + b.y, s0.z + b.z, s0.w + b.w};
            float o1[4] = {s1.x + b.x, s1.y + b.y, s1.z + b.z, s1.w + b.w};
#pragma unroll
            for (int i = 0; i < 4; i++) {
                int c = 4 * cg + i;
                if (c < DOUT) {
                    out[r0 * DOUT + c]       = o0[i];
                    out[(r0 + 1) * DOUT + c] = o1[i];
                }
            }
        }
    }
}

// ---- GRU recurrence: unit-threads. thread = (unit u, K-quarter s).
//      3 gate rows per thread, h reused 3x, shfl combine, 1 barrier/step. ----
__device__ __forceinline__ float fast_sigmoid(float x) {
    return 1.f / (1.f + __expf(-x));
}
__device__ __forceinline__ float fast_tanh(float x) {
    float e = __expf(-2.f * x);
    return (1.f - e) / (1.f + e);
}
__device__ __forceinline__ void fma2(ull& acc, ull h, ull w) {
    asm("fma.rn.f32x2 %0, %1, %2, %0;" : "+l"(acc) : "l"(h), "l"(w));
}
__device__ __forceinline__ float pairsum(ull acc) {
    float lo, hi;
    asm("mov.b64 {%0, %1}, %2;" : "=f"(lo), "=f"(hi) : "l"(acc));
    return lo + hi;
}

__global__ __launch_bounds__(GBLK, 1) void gru_kernel(const float* __restrict__ b_hh)
{
    __shared__ __align__(16) float hbuf[2][HPW];   // ping-pong hidden state
    __shared__ ull tailw[9][GBLK];                 // 3 tail pairs x 3 rows

    const int tid = threadIdx.x;
    const int u = tid >> 2;          // unit 0..135
    const int s = tid & 3;           // K-quarter: pairs [17s, 17s+17)
    const bool uv = (u < HGRU);
    const int urow = uv ? u : 0;

    // weights: rows u, u+131, u+262; 14 pairs in regs + 3 pairs in smem each
    ull wreg[3][14];
#pragma unroll
    for (int g = 0; g < 3; g++) {
        const ull* wp = reinterpret_cast<const ull*>(
            g_wpad + (g * HGRU + urow) * HPW) + s * 17;
#pragma unroll
        for (int q = 0; q < 14; q++) wreg[g][q] = wp[q];
#pragma unroll
        for (int q = 0; q < 3; q++) tailw[g * 3 + q][tid] = wp[14 + q];
    }

    float bh0 = 0.f, bh1 = 0.f, bh2 = 0.f;
    float gi0 = 0.f, gi1 = 0.f, gi2 = 0.f;
    if (uv && s == 0) {
        bh0 = b_hh[u];
        bh1 = b_hh[u + HGRU];
        bh2 = b_hh[u + 2 * HGRU];
        gi0 = g_gi[u];
        gi1 = g_gi[u + HGRU];
        gi2 = g_gi[u + 2 * HGRU];
    }
    if (tid < HPW) { hbuf[0][tid] = 0.f; hbuf[1][tid] = 0.f; }
    __syncthreads();

    int p = 0;
    for (int n = 0; n < NSEQ; n++) {
        const ull* hp = reinterpret_cast<const ull*>(hbuf[p]) + s * 17;

        ull acc0 = 0ULL, acc1 = 0ULL, acc2 = 0ULL;
#pragma unroll
        for (int q = 0; q < 14; q++) {
            ull h = hp[q];
            fma2(acc0, h, wreg[0][q]);
            fma2(acc1, h, wreg[1][q]);
            fma2(acc2, h, wreg[2][q]);
        }
#pragma unroll
        for (int q = 0; q < 3; q++) {
            ull h = hp[14 + q];
            fma2(acc0, h, tailw[q][tid]);
            fma2(acc1, h, tailw[3 + q][tid]);
            fma2(acc2, h, tailw[6 + q][tid]);
        }
        float d0 = pairsum(acc0);
        float d1 = pairsum(acc1);
        float d2 = pairsum(acc2);
        d0 += __shfl_xor_sync(0xffffffffu, d0, 1);
        d0 += __shfl_xor_sync(0xffffffffu, d0, 2);
        d1 += __shfl_xor_sync(0xffffffffu, d1, 1);
        d1 += __shfl_xor_sync(0xffffffffu, d1, 2);
        d2 += __shfl_xor_sync(0xffffffffu, d2, 1);
        d2 += __shfl_xor_sync(0xffffffffu, d2, 2);

        if (uv && s == 0) {
            float r  = fast_sigmoid(gi0 + d0 + bh0);
            float z  = fast_sigmoid(gi1 + d1 + bh1);
            float nn = fast_tanh(gi2 + r * (d2 + bh2));
            float hprev = hbuf[p][u];
            float hnew = nn + z * (hprev - nn);
            hbuf[p ^ 1][u] = hnew;
            g_x[n * HP + u] = hnew;
            if (n + 1 < NSEQ) {                  // prefetch next gi
                gi0 = g_gi[(n + 1) * G3 + u];
                gi1 = g_gi[(n + 1) * G3 + u + HGRU];
                gi2 = g_gi[(n + 1) * G3 + u + 2 * HGRU];
            }
        }
        __syncthreads();
        p ^= 1;
    }
}

// ---- dummy: shifts gru_kernel into profiled launch slot #4 ----
__global__ void dummy_kernel() {}

extern "C" void kernel_launch(void* const* d_in, const int* in_sizes, int n_in,
                              void* d_out, int out_size)
{
    const float* history = (const float*)d_in[0];
    const float* W_ih = (const float*)d_in[1];
    const float* W_hh = (const float*)d_in[2];
    const float* b_ih = (const float*)d_in[3];
    const float* b_hh = (const float*)d_in[4];
    const float* W1 = (const float*)d_in[5];  const float* b1 = (const float*)d_in[6];
    const float* W2 = (const float*)d_in[7];  const float* b2 = (const float*)d_in[8];
    const float* W3 = (const float*)d_in[9];  const float* b3 = (const float*)d_in[10];
    const float* W4 = (const float*)d_in[11]; const float* b4 = (const float*)d_in[12];
    const float* W5 = (const float*)d_in[13]; const float* b5 = (const float*)d_in[14];
    const float* W6 = (const float*)d_in[15]; const float* b6 = (const float*)d_in[16];
    float* out = (float*)d_out;

    const int prep_total = G3 * HGRU + G3 * FIN + G3 + DMLP * HGRU
                         + 4 * DMLP * DMLP + 5 * DMLP + DOUT * DMLP + DOUT;

    dummy_kernel<<<1, 32>>>();                                      // launch 1
    prep_kernel<<<(prep_total + 511) / 512, 512>>>(                 // launch 2
        W_hh, W_ih, b_ih, W1, b1, W2, b2, W3, b3, W4, b4, W5, b5, W6, b6);
    gi_kernel<<<NSEQ / 2, G3P>>>(history);                          // launch 3
    gru_kernel<<<1, GBLK>>>(b_hh);                                  // launch 4 (profiled)
    mlp_kernel<<<NSEQ / 2, 512>>>(out);                             // launch 5
}

// round 11
// speedup vs baseline: 1.3812x; 1.3812x over previous
#include <cuda_runtime.h>
#include <cstdint>

#define NSEQ 128
#define TB   4096
#define FIN  208
#define HGRU 131
#define HP   132      // activation pitch (g_x)
#define HPW  136      // W_hh row pitch (34 quads; cols 131..135 zero)
#define G3   393      // 3*H
#define G3P  416      // padded 3*H
#define DMLP 255
#define DOUT 17

#define NREGP 48      // GRU weight pairs in registers (96 floats = 24 quads)
#define NTAIL 18      // GRU weight pairs in transposed smem (9 quads)

typedef unsigned long long ull;

// ---- scratch (__device__ globals; zero-initialized; pads never written) ----
__device__ float g_wpad[G3 * HPW];       // W_hh padded [393][136]
__device__ float g_gi[NSEQ * G3];
__device__ float g_x[NSEQ * HP];         // GRU outputs, pitch 132
__device__ float g_wiht[FIN * G3P];      // W_ih^T [208][416]
__device__ float g_bihp[G3P];
__device__ float g_wmt[5][256 * 256];    // W1..W5 transposed [k][c]
__device__ float g_bmp[5][256];
__device__ float g_w6t[256 * 32];        // W6^T [k][c]
__device__ float g_b6p[32];

// ---- prep: coalesced reads, scattered writes ----
__global__ void prep_kernel(const float* __restrict__ Whh,
                            const float* __restrict__ Wih,
                            const float* __restrict__ bih,
                            const float* __restrict__ W1, const float* __restrict__ b1,
                            const float* __restrict__ W2, const float* __restrict__ b2,
                            const float* __restrict__ W3, const float* __restrict__ b3,
                            const float* __restrict__ W4, const float* __restrict__ b4,
                            const float* __restrict__ W5, const float* __restrict__ b5,
                            const float* __restrict__ W6, const float* __restrict__ b6)
{
    int idx = blockIdx.x * blockDim.x + threadIdx.x;

    if (idx < G3 * HGRU) {
        int j = idx / HGRU, k = idx - j * HGRU;
        g_wpad[j * HPW + k] = Whh[idx];
        return;
    }
    idx -= G3 * HGRU;
    if (idx < G3 * FIN) {
        int j = idx / FIN, k = idx - j * FIN;
        g_wiht[k * G3P + j] = Wih[idx];
        return;
    }
    idx -= G3 * FIN;
    if (idx < G3) { g_bihp[idx] = bih[idx]; return; }
    idx -= G3;
    if (idx < DMLP * HGRU) {
        int c = idx / HGRU, k = idx - c * HGRU;
        g_wmt[0][k * 256 + c] = W1[idx];
        return;
    }
    idx -= DMLP * HGRU;
    if (idx < 4 * DMLP * DMLP) {
        int l = idx / (DMLP * DMLP);
        int r = idx - l * (DMLP * DMLP);
        int c = r / DMLP, k = r - c * DMLP;
        const float* W = (l == 0) ? W2 : (l == 1) ? W3 : (l == 2) ? W4 : W5;
        g_wmt[l + 1][k * 256 + c] = W[r];
        return;
    }
    idx -= 4 * DMLP * DMLP;
    if (idx < 5 * DMLP) {
        int l = idx / DMLP, c = idx - l * DMLP;
        const float* B = (l == 0) ? b1 : (l == 1) ? b2 : (l == 2) ? b3
                        : (l == 3) ? b4 : b5;
        g_bmp[l][c] = B[c];
        return;
    }
    idx -= 5 * DMLP;
    if (idx < DOUT * DMLP) {
        int c = idx / DMLP, k = idx - c * DMLP;
        g_w6t[k * 32 + c] = W6[idx];
        return;
    }
    idx -= DOUT * DMLP;
    if (idx < DOUT) g_b6p[idx] = b6[idx];
}

// ---- gi projection ----
__global__ __launch_bounds__(G3P) void gi_kernel(const float* __restrict__ hist)
{
    __shared__ float2 xs[FIN];
    const int j = threadIdx.x;
    const int r0 = blockIdx.x * 2;

    const float* h0 = hist + ((size_t)r0 * TB + (TB - 1)) * FIN;
    const float* h1 = hist + ((size_t)(r0 + 1) * TB + (TB - 1)) * FIN;
    for (int k = j; k < FIN; k += G3P) xs[k] = make_float2(h0[k], h1[k]);
    __syncthreads();

    float bv = g_bihp[j];
    float a0 = bv, a1 = bv;
#pragma unroll 16
    for (int k = 0; k < FIN; k++) {
        float w = g_wiht[k * G3P + j];
        float2 x = xs[k];
        a0 = fmaf(x.x, w, a0);
        a1 = fmaf(x.y, w, a1);
    }
    if (j < G3) {
        g_gi[r0 * G3 + j]       = a0;
        g_gi[(r0 + 1) * G3 + j] = a1;
    }
}

// ---- fused 6-layer MLP (unchanged from R9) ----
__global__ __launch_bounds__(512) void mlp_kernel(float* __restrict__ out)
{
    __shared__ float2 xbuf[256];
    __shared__ float4 red[8][64][2];
    const int tid = threadIdx.x;
    const int cg = tid & 63;
    const int ks = tid >> 6;
    const int r0 = blockIdx.x * 2;
    const int kbase = ks * 32;

    if (tid < 256) {
        float2 v = make_float2(0.f, 0.f);
        if (tid < HGRU)
            v = make_float2(g_x[r0 * HP + tid], g_x[(r0 + 1) * HP + tid]);
        xbuf[tid] = v;
    }
    __syncthreads();

#pragma unroll
    for (int l = 0; l < 5; l++) {
        const float4* wt4 = reinterpret_cast<const float4*>(g_wmt[l]);
        float4 a0 = make_float4(0.f, 0.f, 0.f, 0.f);
        float4 a1 = a0;
#pragma unroll
        for (int g = 0; g < 4; g++) {
            float4 wb[8];
            float2 xb[8];
#pragma unroll
            for (int u = 0; u < 8; u++) {
                int k = kbase + g * 8 + u;
                wb[u] = wt4[k * 64 + cg];
                xb[u] = xbuf[k];
            }
#pragma unroll
            for (int u = 0; u < 8; u++) {
                a0.x = fmaf(xb[u].x, wb[u].x, a0.x);
                a0.y = fmaf(xb[u].x, wb[u].y, a0.y);
                a0.z = fmaf(xb[u].x, wb[u].z, a0.z);
                a0.w = fmaf(xb[u].x, wb[u].w, a0.w);
                a1.x = fmaf(xb[u].y, wb[u].x, a1.x);
                a1.y = fmaf(xb[u].y, wb[u].y, a1.y);
                a1.z = fmaf(xb[u].y, wb[u].z, a1.z);
                a1.w = fmaf(xb[u].y, wb[u].w, a1.w);
            }
        }
        red[ks][cg][0] = a0;
        red[ks][cg][1] = a1;
        __syncthreads();
        if (ks == 0) {
            float4 s0 = red[0][cg][0], s1 = red[0][cg][1];
#pragma unroll
            for (int q = 1; q < 8; q++) {
                float4 t0 = red[q][cg][0], t1 = red[q][cg][1];
                s0.x += t0.x; s0.y += t0.y; s0.z += t0.z; s0.w += t0.w;
                s1.x += t1.x; s1.y += t1.y; s1.z += t1.z; s1.w += t1.w;
            }
            float4 b = reinterpret_cast<const float4*>(g_bmp[l])[cg];
            xbuf[4 * cg + 0] = make_float2(fmaxf(s0.x + b.x, 0.f), fmaxf(s1.x + b.x, 0.f));
            xbuf[4 * cg + 1] = make_float2(fmaxf(s0.y + b.y, 0.f), fmaxf(s1.y + b.y, 0.f));
            xbuf[4 * cg + 2] = make_float2(fmaxf(s0.z + b.z, 0.f), fmaxf(s1.z + b.z, 0.f));
            xbuf[4 * cg + 3] = make_float2(fmaxf(s0.w + b.w, 0.f), fmaxf(s1.w + b.w, 0.f));
        }
        __syncthreads();
    }

    {
        const float4* w6 = reinterpret_cast<const float4*>(g_w6t);
        float4 a0 = make_float4(0.f, 0.f, 0.f, 0.f);
        float4 a1 = a0;
        if (cg < 8) {
#pragma unroll
            for (int g = 0; g < 4; g++) {
                float4 wb[8];
                float2 xb[8];
#pragma unroll
                for (int u = 0; u < 8; u++) {
                    int k = kbase + g * 8 + u;
                    wb[u] = w6[k * 8 + cg];
                    xb[u] = xbuf[k];
                }
#pragma unroll
                for (int u = 0; u < 8; u++) {
                    a0.x = fmaf(xb[u].x, wb[u].x, a0.x);
                    a0.y = fmaf(xb[u].x, wb[u].y, a0.y);
                    a0.z = fmaf(xb[u].x, wb[u].z, a0.z);
                    a0.w = fmaf(xb[u].x, wb[u].w, a0.w);
                    a1.x = fmaf(xb[u].y, wb[u].x, a1.x);
                    a1.y = fmaf(xb[u].y, wb[u].y, a1.y);
                    a1.z = fmaf(xb[u].y, wb[u].z, a1.z);
                    a1.w = fmaf(xb[u].y, wb[u].w, a1.w);
                }
            }
        }
        red[ks][cg][0] = a0;
        red[ks][cg][1] = a1;
        __syncthreads();
        if (ks == 0 && cg < 5) {
            float4 s0 = red[0][cg][0], s1 = red[0][cg][1];
#pragma unroll
            for (int q = 1; q < 8; q++) {
                float4 t0 = red[q][cg][0], t1 = red[q][cg][1];
                s0.x += t0.x; s0.y += t0.y; s0.z += t0.z; s0.w += t0.w;
                s1.x += t1.x; s1.y += t1.y; s1.z += t1.z; s1.w += t1.w;
            }
            float4 b = reinterpret_cast<const float4*>(g_b6p)[cg];
            float o0[4] = {s0.x + b.x, s0.y + b.y, s0.z + b.z, s0.w + b.w};
            float o1[4] = {s1.x + b.x, s1.y + b.y, s1.z + b.z, s1.w + b.w};
#pragma unroll
            for (int i = 0; i < 4; i++) {
                int c = 4 * cg + i;
                if (c < DOUT) {
                    out[r0 * DOUT + c]       = o0[i];
                    out[(r0 + 1) * DOUT + c] = o1[i];
                }
            }
        }
    }
}

// ---- GRU recurrence: R9 structure + volatile-staged loads + tanh.approx ----
__device__ __forceinline__ float tanh_fast(float x) {
    float y;
    asm("tanh.approx.f32 %0, %1;" : "=f"(y) : "f"(x));
    return y;
}
__device__ __forceinline__ float sigmoid_fast(float x) {
    return fmaf(0.5f, tanh_fast(0.5f * x), 0.5f);
}
__device__ __forceinline__ void fma2(ull& acc, ull h, ull w) {
    asm("fma.rn.f32x2 %0, %1, %2, %0;" : "+l"(acc) : "l"(h), "l"(w));
}

// volatile LDS.128 of one 16B quad (2 ulls) at byte offset off from h base
#define LDSQ(t0, t1, off)                                            \
    asm volatile("ld.shared.v2.u64 {%0, %1}, [%2];"                  \
                 : "=l"(t0), "=l"(t1) : "r"(h_addr + (off)))

__global__ __launch_bounds__(G3P, 1) void gru_kernel(const float* __restrict__ b_hh)
{
    __shared__ __align__(16) float h_sh[HP];     // 33 quads
    __shared__ float gh_sh[G3];
    __shared__ float gi_sh[G3];
    __shared__ ull tail_w[NTAIL][G3P];

    const int j = threadIdx.x;

    ull w2[NREGP];
    float bj = 0.f;
    if (j < G3) {
        const ull* wr = reinterpret_cast<const ull*>(g_wpad + j * HPW);
#pragma unroll
        for (int i = 0; i < NREGP; i++) w2[i] = wr[i];
#pragma unroll
        for (int t = 0; t < NTAIL; t++) tail_w[t][j] = wr[NREGP + t];
        bj = b_hh[j];
    }
    if (j < HP) h_sh[j] = 0.f;

    uint32_t h_addr;
    asm("{ .reg .u64 t; cvta.to.shared.u64 t, %1; cvt.u32.u64 %0, t; }"
        : "=r"(h_addr) : "l"(h_sh));

    float gi_v = (j < G3) ? g_gi[j] : 0.f;
    __syncthreads();

    const ulonglong2* hv2 = reinterpret_cast<const ulonglong2*>(h_sh);

    for (int n = 0; n < NSEQ; n++) {
        float gi_cur = gi_v;
        if (j < G3 && n + 1 < NSEQ) gi_v = __ldg(g_gi + (n + 1) * G3 + j);

        if (j < G3) {
            ull acc0, acc1 = 0ULL;
            asm("mov.b64 %0, {%1, %2};" : "=l"(acc0) : "f"(bj), "f"(0.f));
            // register part: quads 0..23 in 6 volatile-staged groups of 4
#pragma unroll
            for (int g = 0; g < 6; g++) {
                ull t0, t1, t2, t3, t4, t5, t6, t7;
                LDSQ(t0, t1, (4 * g + 0) * 16);
                LDSQ(t2, t3, (4 * g + 1) * 16);
                LDSQ(t4, t5, (4 * g + 2) * 16);
                LDSQ(t6, t7, (4 * g + 3) * 16);
                fma2(acc0, t0, w2[8 * g + 0]); fma2(acc1, t1, w2[8 * g + 1]);
                fma2(acc0, t2, w2[8 * g + 2]); fma2(acc1, t3, w2[8 * g + 3]);
                fma2(acc0, t4, w2[8 * g + 4]); fma2(acc1, t5, w2[8 * g + 5]);
                fma2(acc0, t6, w2[8 * g + 6]); fma2(acc1, t7, w2[8 * g + 7]);
            }
            // smem tail: quads 24..32 (plain loads; ptxas schedules freely)
#pragma unroll
            for (int t = 0; t < 9; t += 3) {
                ulonglong2 h0 = hv2[24 + t];
                ulonglong2 h1 = hv2[25 + t];
                ulonglong2 h2 = hv2[26 + t];
                ull wa = tail_w[2 * t + 0][j], wb = tail_w[2 * t + 1][j];
                ull wc = tail_w[2 * t + 2][j], wd = tail_w[2 * t + 3][j];
                ull we = tail_w[2 * t + 4][j], wf = tail_w[2 * t + 5][j];
                fma2(acc0, h0.x, wa); fma2(acc1, h0.y, wb);
                fma2(acc0, h1.x, wc); fma2(acc1, h1.y, wd);
                fma2(acc0, h2.x, we); fma2(acc1, h2.y, wf);
            }
            float a0, a1, a2, a3;
            asm("mov.b64 {%0, %1}, %2;" : "=f"(a0), "=f"(a1) : "l"(acc0));
            asm("mov.b64 {%0, %1}, %2;" : "=f"(a2), "=f"(a3) : "l"(acc1));
            gh_sh[j] = (a0 + a2) + (a1 + a3);
            gi_sh[j] = gi_cur;
        }
        __syncthreads();

        if (j < HGRU) {
            float ir = gi_sh[j], iz = gi_sh[j + HGRU], in_ = gi_sh[j + 2 * HGRU];
            float hr = gh_sh[j], hz = gh_sh[j + HGRU], hn = gh_sh[j + 2 * HGRU];
            float r  = sigmoid_fast(ir + hr);
            float z  = sigmoid_fast(iz + hz);
            float nn = tanh_fast(in_ + r * hn);
            float hp = h_sh[j];
            float hnew = nn + z * (hp - nn);
            h_sh[j] = hnew;
            g_x[n * HP + j] = hnew;
        }
        __syncthreads();
    }
}

// ---- dummy: shifts gru_kernel into profiled launch slot #4 ----
__global__ void dummy_kernel() {}

extern "C" void kernel_launch(void* const* d_in, const int* in_sizes, int n_in,
                              void* d_out, int out_size)
{
    const float* history = (const float*)d_in[0];
    const float* W_ih = (const float*)d_in[1];
    const float* W_hh = (const float*)d_in[2];
    const float* b_ih = (const float*)d_in[3];
    const float* b_hh = (const float*)d_in[4];
    const float* W1 = (const float*)d_in[5];  const float* b1 = (const float*)d_in[6];
    const float* W2 = (const float*)d_in[7];  const float* b2 = (const float*)d_in[8];
    const float* W3 = (const float*)d_in[9];  const float* b3 = (const float*)d_in[10];
    const float* W4 = (const float*)d_in[11]; const float* b4 = (const float*)d_in[12];
    const float* W5 = (const float*)d_in[13]; const float* b5 = (const float*)d_in[14];
    const float* W6 = (const float*)d_in[15]; const float* b6 = (const float*)d_in[16];
    float* out = (float*)d_out;

    const int prep_total = G3 * HGRU + G3 * FIN + G3 + DMLP * HGRU
                         + 4 * DMLP * DMLP + 5 * DMLP + DOUT * DMLP + DOUT;

    dummy_kernel<<<1, 32>>>();                                      // launch 1
    prep_kernel<<<(prep_total + 511) / 512, 512>>>(                 // launch 2
        W_hh, W_ih, b_ih, W1, b1, W2, b2, W3, b3, W4, b4, W5, b5, W6, b6);
    gi_kernel<<<NSEQ / 2, G3P>>>(history);                          // launch 3
    gru_kernel<<<1, G3P>>>(b_hh);                                   // launch 4 (profiled)
    mlp_kernel<<<NSEQ / 2, 512>>>(out);                             // launch 5
}